// round 14
// baseline (speedup 1.0000x reference)
#include <cuda_runtime.h>
#include <cuda_fp16.h>
#include <math.h>
#include <stdint.h>

#define BB 8
#define CC 512
#define SS 1024
#define HH 8
#define DD 64
#define MM (BB*SS)

#define QSCALE (0.125f * 1.44269504088896340736f)   // 1/(8 ln2) -> softmax via exp2

// ---------------------------------------------------------------------------
// Scratch (device globals) — fp16 storage
// ---------------------------------------------------------------------------
__device__ __half g_tn[MM*CC];       // LN output  [m][c]
__device__ __half g_q [MM*CC];       // Q [bh][s][d] (pre-scaled)
__device__ __half g_k [MM*CC];       // K [bh][s][d]
__device__ __half g_v [MM*CC];       // V [bh][s][d]
__device__ __half g_ao[MM*CC];       // attn out [m][512]
__device__ __half g_w[4][CC*CC];     // transposed weights [n][k]; 0..2 contiguous = Wqkv[1536][512]

// ---------------------------------------------------------------------------
// helpers
// ---------------------------------------------------------------------------
__device__ __forceinline__ uint32_t s2u(const void* p) {
    uint32_t a;
    asm("{ .reg .u64 t; cvta.to.shared.u64 t, %1; cvt.u32.u64 %0, t; }" : "=r"(a) : "l"(p));
    return a;
}
__device__ __forceinline__ float ex2f(float x) {
    float y; asm("ex2.approx.f32 %0, %1;" : "=f"(y) : "f"(x)); return y;
}
__device__ __forceinline__ uint32_t packh2(float a, float b) {
    __half2 h = __floats2half2_rn(a, b);
    return *(uint32_t*)&h;
}
__device__ __forceinline__ void ldm4(uint32_t r[4], uint32_t addr) {
    asm volatile("ldmatrix.sync.aligned.m8n8.x4.shared.b16 {%0,%1,%2,%3}, [%4];"
        : "=r"(r[0]), "=r"(r[1]), "=r"(r[2]), "=r"(r[3]) : "r"(addr));
}
__device__ __forceinline__ void ldm4t(uint32_t r[4], uint32_t addr) {
    asm volatile("ldmatrix.sync.aligned.m8n8.x4.trans.shared.b16 {%0,%1,%2,%3}, [%4];"
        : "=r"(r[0]), "=r"(r[1]), "=r"(r[2]), "=r"(r[3]) : "r"(addr));
}
__device__ __forceinline__ void mma_f32(float c[4], const uint32_t a[4], const uint32_t b[2]) {
    asm volatile("mma.sync.aligned.m16n8k16.row.col.f32.f16.f16.f32 "
        "{%0,%1,%2,%3}, {%4,%5,%6,%7}, {%8,%9}, {%0,%1,%2,%3};"
        : "+f"(c[0]), "+f"(c[1]), "+f"(c[2]), "+f"(c[3])
        : "r"(a[0]), "r"(a[1]), "r"(a[2]), "r"(a[3]), "r"(b[0]), "r"(b[1]));
}
__device__ __forceinline__ void cpa16(uint32_t s, const void* g) {
    asm volatile("cp.async.cg.shared.global [%0], [%1], 16;" :: "r"(s), "l"(g));
}
#define CP_COMMIT() asm volatile("cp.async.commit_group;" ::: "memory")
template <int N> __device__ __forceinline__ void cpwait() {
    asm volatile("cp.async.wait_group %0;" :: "n"(N) : "memory");
}

// ---------------------------------------------------------------------------
// Fused prep: blocks 0..1023 = weight transpose, 1024..1535 = transpose+LN
// ---------------------------------------------------------------------------
__global__ __launch_bounds__(256) void prep_kernel(
        const float* __restrict__ wq, const float* __restrict__ wk,
        const float* __restrict__ wv, const float* __restrict__ wo,
        const float* __restrict__ x,
        const float* __restrict__ lng, const float* __restrict__ lnb) {
    __shared__ float smem[16*513 + 32];
    const int tid = threadIdx.x;
    const int bid = blockIdx.x;

    if (bid < 1024) {
        float (*t)[33] = (float(*)[33])smem;
        const int z   = bid >> 8;
        const int rem = bid & 255;
        const int k0 = (rem >> 4) * 32, n0 = (rem & 15) * 32;
        const float* src = z==0 ? wq : z==1 ? wk : z==2 ? wv : wo;
        __half* dst = g_w[z];
        const int c = tid & 31, r8 = tid >> 5;
        #pragma unroll
        for (int i = 0; i < 4; i++) {
            int r = r8 + i*8;
            t[r][c] = src[(k0+r)*CC + n0 + c];
        }
        __syncthreads();
        #pragma unroll
        for (int i = 0; i < 4; i++) {
            int r = r8 + i*8;
            dst[(n0+r)*CC + k0 + c] = __float2half(t[c][r]);
        }
    } else {
        float (*tile)[513] = (float(*)[513])smem;
        float* s_mean = smem + 16*513;
        float* s_rstd = s_mean + 16;
        const int id = bid - 1024;
        const int b  = id >> 6;
        const int s0 = (id & 63) * 16;

        const int sI = tid & 15;
        const int cB = tid >> 4;
        for (int c = cB; c < CC; c += 16)
            tile[sI][c] = x[(b*CC + c)*SS + s0 + sI];
        __syncthreads();

        const int w = tid >> 5, lane = tid & 31;
        for (int s = w; s < 16; s += 8) {
            float sum = 0.f, sq = 0.f;
            for (int c = lane; c < CC; c += 32) {
                float v = tile[s][c];
                sum += v; sq += v*v;
            }
            #pragma unroll
            for (int off = 16; off; off >>= 1) {
                sum += __shfl_xor_sync(0xffffffffu, sum, off);
                sq  += __shfl_xor_sync(0xffffffffu, sq,  off);
            }
            if (lane == 0) {
                float mu = sum * (1.f/CC);
                s_mean[s] = mu;
                s_rstd[s] = rsqrtf(sq*(1.f/CC) - mu*mu + 1e-5f);
            }
        }
        __syncthreads();

        for (int i = tid; i < 16*256; i += 256) {
            int s  = i >> 8;
            int c2 = (i & 255) * 2;
            float v0 = (tile[s][c2  ] - s_mean[s]) * s_rstd[s] * lng[c2  ] + lnb[c2  ];
            float v1 = (tile[s][c2+1] - s_mean[s]) * s_rstd[s] * lng[c2+1] + lnb[c2+1];
            *(uint32_t*)&g_tn[((b<<10) + s0 + s)*CC + c2] = packh2(v0, v1);
        }
    }
}

// ---------------------------------------------------------------------------
// fp16 mma.sync GEMM: BM=128 BN=128 BK=64, 128 threads (4 warps, 2M x 2N),
// warp tile 64x64, f32 accum, cp.async 2-stage STATIC smem, one barrier/chunk.
//  MODE 0: A=g_tn, W=Wqkv fused -> Q/K/V [bh][s][d]
//  MODE 1: A=g_ao, W=g_w[3] -> fp32 out + bias + residual(x transposed read)
// ---------------------------------------------------------------------------
template <int MODE>
__global__ __launch_bounds__(128, 2) void mm_kernel(
        const float* __restrict__ bq, const float* __restrict__ bk,
        const float* __restrict__ bv, const float* __restrict__ bo,
        const float* __restrict__ x,  float* __restrict__ dout) {

    __shared__ __half sA[2][128][72];
    __shared__ __half sB[2][128][72];

    const int tid  = threadIdx.x;
    const int lane = tid & 31;
    const int wid  = tid >> 5;
    const int wm   = wid & 1;
    const int wn   = wid >> 1;
    const int m0 = blockIdx.y * 128;
    const int n0 = blockIdx.x * 128;
    const int z  = (MODE == 0) ? (n0 >> 9) : 3;

    const __half* A = (MODE == 0) ? g_tn : g_ao;
    const __half* W = (MODE == 0) ? (g_w[0] + (size_t)n0 * CC)
                                  : (g_w[3] + (size_t)n0 * CC);
    const float* bias = (MODE == 0) ? (z==0 ? bq : z==1 ? bk : bv) : bo;

    float acc[4][8][4];
    #pragma unroll
    for (int i = 0; i < 4; i++)
        #pragma unroll
        for (int j = 0; j < 8; j++)
            #pragma unroll
            for (int q = 0; q < 4; q++) acc[i][j][q] = 0.f;

    auto issue = [&](int st, int k0) {
        #pragma unroll
        for (int i = 0; i < 8; i++) {
            int idx = tid + i*128;
            int row = idx >> 3, seg = idx & 7;
            cpa16(s2u(&sA[st][row][seg*8]), &A[(m0+row)*CC + k0 + seg*8]);
            cpa16(s2u(&sB[st][row][seg*8]), &W[row*CC + k0 + seg*8]);
        }
        CP_COMMIT();
    };

    issue(0, 0);

    for (int kc = 0; kc < 8; kc++) {
        const int st = kc & 1;
        cpwait<0>();
        __syncthreads();
        if (kc < 7) issue(st^1, (kc+1)*64);

        #pragma unroll
        for (int kk = 0; kk < 64; kk += 16) {
            uint32_t af[4][4];
            #pragma unroll
            for (int mt = 0; mt < 4; mt++)
                ldm4(af[mt], s2u(&sA[st][wm*64 + mt*16 + (lane & 15)]
                                        [kk + (lane >> 4)*8]));
            #pragma unroll
            for (int p = 0; p < 4; p++) {
                uint32_t b4[4];
                ldm4(b4, s2u(&sB[st][wn*64 + (p*2 + (lane >> 4))*8 + (lane & 7)]
                                     [kk + ((lane >> 3) & 1)*8]));
                #pragma unroll
                for (int mt = 0; mt < 4; mt++) {
                    mma_f32(acc[mt][2*p  ], af[mt], b4);
                    mma_f32(acc[mt][2*p+1], af[mt], b4+2);
                }
            }
        }
    }

    // epilogue
    #pragma unroll
    for (int mt = 0; mt < 4; mt++) {
        const int r0 = m0 + wm*64 + mt*16 + (lane >> 2);
        const int r1 = r0 + 8;
        const int b0r = r0 >> 10, s0r = r0 & 1023;
        const int b1r = r1 >> 10, s1r = r1 & 1023;
        #pragma unroll
        for (int nt = 0; nt < 8; nt++) {
            const int c  = n0 + wn*64 + nt*8 + (lane & 3)*2;
            const int cz = c & 511;
            float v00 = acc[mt][nt][0] + bias[cz];
            float v01 = acc[mt][nt][1] + bias[cz+1];
            float v10 = acc[mt][nt][2] + bias[cz];
            float v11 = acc[mt][nt][3] + bias[cz+1];

            if (MODE == 0) {
                const int h = cz >> 6, d = c & 63;
                if (z == 0) { v00 *= QSCALE; v01 *= QSCALE; v10 *= QSCALE; v11 *= QSCALE; }
                __half* o = (z == 0) ? g_q : (z == 1) ? g_k : g_v;
                *(uint32_t*)&o[(((b0r*HH + h) << 10) + s0r)*DD + d] = packh2(v00, v01);
                *(uint32_t*)&o[(((b1r*HH + h) << 10) + s1r)*DD + d] = packh2(v10, v11);
            } else {
                float2 o0, o1;
                o0.x = v00 + x[(b0r*CC + c    )*SS + s0r];
                o0.y = v01 + x[(b0r*CC + c + 1)*SS + s0r];
                o1.x = v10 + x[(b1r*CC + c    )*SS + s1r];
                o1.y = v11 + x[(b1r*CC + c + 1)*SS + s1r];
                *(float2*)&dout[r0*CC + c] = o0;
                *(float2*)&dout[r1*CC + c] = o1;
            }
        }
    }
}

// ---------------------------------------------------------------------------
// FA2 attention: fp16 in / f32 accum, 128 threads, 4 warps x 32 q-rows,
// cp.async 2-stage, one barrier per k-tile. NOW 3 CTAs/SM for latency cover.
// ---------------------------------------------------------------------------
__global__ __launch_bounds__(128, 3) void attn_kernel() {
    __shared__ __half sKV[2][2][64][72];   // [stage][0=K,1=V][s][d]

    const int tid  = threadIdx.x;
    const int lane = tid & 31;
    const int wid  = tid >> 5;
    const int bh   = blockIdx.y;
    const int q0   = blockIdx.x * 128;

    const __half* qg = g_q + (size_t)bh * SS * DD;
    const __half* kg = g_k + (size_t)bh * SS * DD;
    const __half* vg = g_v + (size_t)bh * SS * DD;

    __half (*sQ)[72] = reinterpret_cast<__half(*)[72]>(&sKV[0][0][0][0]);
    #pragma unroll
    for (int i = 0; i < 8; i++) {
        int idx = tid + i*128;
        int row = idx >> 3, seg = idx & 7;
        *(uint4*)&sQ[row][seg*8] = *(const uint4*)&qg[(q0+row)*DD + seg*8];
    }
    __syncthreads();
    uint32_t qf[2][4][4];
    #pragma unroll
    for (int mt = 0; mt < 2; mt++)
        #pragma unroll
        for (int ks = 0; ks < 4; ks++)
            ldm4(qf[mt][ks], s2u(&sQ[wid*32 + mt*16 + (lane & 15)]
                                    [ks*16 + (lane >> 4)*8]));
    __syncthreads();

    float o[2][8][4];
    #pragma unroll
    for (int mt = 0; mt < 2; mt++)
        #pragma unroll
        for (int i = 0; i < 8; i++)
            #pragma unroll
            for (int j = 0; j < 4; j++) o[mt][i][j] = 0.f;
    float lA[2] = {0.f, 0.f}, lB[2] = {0.f, 0.f};

    auto issue = [&](int st, int kt) {
        const int s0 = kt * 64;
        #pragma unroll
        for (int i = 0; i < 4; i++) {
            int idx = tid + i*128;
            int row = idx >> 3, seg = idx & 7;
            cpa16(s2u(&sKV[st][0][row][seg*8]), &kg[(s0+row)*DD + seg*8]);
            cpa16(s2u(&sKV[st][1][row][seg*8]), &vg[(s0+row)*DD + seg*8]);
        }
        CP_COMMIT();
    };

    issue(0, 0);

    for (int kt = 0; kt < 16; kt++) {
        const int st = kt & 1;
        cpwait<0>();
        __syncthreads();
        if (kt < 15) issue(st^1, kt+1);

        #pragma unroll
        for (int j2 = 0; j2 < 4; j2++) {
            float sc[2][2][4];
            #pragma unroll
            for (int mt = 0; mt < 2; mt++)
                #pragma unroll
                for (int n = 0; n < 2; n++)
                    #pragma unroll
                    for (int q = 0; q < 4; q++) sc[mt][n][q] = 0.f;

            #pragma unroll
            for (int ks = 0; ks < 4; ks++) {
                uint32_t b4[4];
                ldm4(b4, s2u(&sKV[st][0][(2*j2 + (lane >> 4))*8 + (lane & 7)]
                                        [ks*16 + ((lane >> 3) & 1)*8]));
                #pragma unroll
                for (int mt = 0; mt < 2; mt++) {
                    mma_f32(sc[mt][0], qf[mt][ks], b4);
                    mma_f32(sc[mt][1], qf[mt][ks], b4+2);
                }
            }

            uint32_t pa[2][4];
            #pragma unroll
            for (int mt = 0; mt < 2; mt++) {
                float e00 = ex2f(sc[mt][0][0]), e01 = ex2f(sc[mt][0][1]);
                float e02 = ex2f(sc[mt][0][2]), e03 = ex2f(sc[mt][0][3]);
                float e10 = ex2f(sc[mt][1][0]), e11 = ex2f(sc[mt][1][1]);
                float e12 = ex2f(sc[mt][1][2]), e13 = ex2f(sc[mt][1][3]);
                lA[mt] += e00 + e01 + e10 + e11;
                lB[mt] += e02 + e03 + e12 + e13;
                pa[mt][0] = packh2(e00, e01);
                pa[mt][1] = packh2(e02, e03);
                pa[mt][2] = packh2(e10, e11);
                pa[mt][3] = packh2(e12, e13);
            }

            #pragma unroll
            for (int p = 0; p < 4; p++) {
                uint32_t v4[4];
                ldm4t(v4, s2u(&sKV[st][1][j2*16 + (lane & 15)]
                                         [(p*2 + (lane >> 4))*8]));
                #pragma unroll
                for (int mt = 0; mt < 2; mt++) {
                    mma_f32(o[mt][2*p  ], pa[mt], v4);
                    mma_f32(o[mt][2*p+1], pa[mt], v4+2);
                }
            }
        }
    }

    const int b = bh >> 3, h = bh & 7;
    #pragma unroll
    for (int mt = 0; mt < 2; mt++) {
        float la = lA[mt], lb = lB[mt];
        la += __shfl_xor_sync(0xffffffffu, la, 1);
        la += __shfl_xor_sync(0xffffffffu, la, 2);
        lb += __shfl_xor_sync(0xffffffffu, lb, 1);
        lb += __shfl_xor_sync(0xffffffffu, lb, 2);
        const float invA = 1.f / la, invB = 1.f / lb;

        const int mA = (b << 10) + q0 + wid*32 + mt*16 + (lane >> 2);
        const int mB = mA + 8;
        #pragma unroll
        for (int nt = 0; nt < 8; nt++) {
            const int d = nt*8 + (lane & 3)*2;
            *(uint32_t*)&g_ao[mA*CC + h*DD + d] =
                packh2(o[mt][nt][0]*invA, o[mt][nt][1]*invA);
            *(uint32_t*)&g_ao[mB*CC + h*DD + d] =
                packh2(o[mt][nt][2]*invB, o[mt][nt][3]*invB);
        }
    }
}

// ---------------------------------------------------------------------------
extern "C" void kernel_launch(void* const* d_in, const int* in_sizes, int n_in,
                              void* d_out, int out_size) {
    const float* x   = (const float*)d_in[0];
    const float* wq  = (const float*)d_in[1];
    const float* bq  = (const float*)d_in[2];
    const float* wk  = (const float*)d_in[3];
    const float* bk  = (const float*)d_in[4];
    const float* wv  = (const float*)d_in[5];
    const float* bv  = (const float*)d_in[6];
    const float* lng = (const float*)d_in[7];
    const float* lnb = (const float*)d_in[8];
    const float* wo  = (const float*)d_in[9];
    const float* bo  = (const float*)d_in[10];
    float* out = (float*)d_out;

    prep_kernel<<<1536, 256>>>(wq, wk, wv, wo, x, lng, lnb);
    mm_kernel<0><<<dim3(12, 64), 128>>>(bq, bk, bv, nullptr, nullptr, nullptr);
    attn_kernel<<<dim3(8, 64), 128>>>();
    mm_kernel<1><<<dim3(4, 64), 128>>>(nullptr, nullptr, nullptr, bo, x, out);
}

// round 15
// speedup vs baseline: 1.0443x; 1.0443x over previous
#include <cuda_runtime.h>
#include <cuda_fp16.h>
#include <math.h>
#include <stdint.h>

#define BB 8
#define CC 512
#define SS 1024
#define HH 8
#define DD 64
#define MM (BB*SS)

#define QSCALE (0.125f * 1.44269504088896340736f)   // 1/(8 ln2) -> softmax via exp2

// ---------------------------------------------------------------------------
// Scratch (device globals) — fp16 storage
// ---------------------------------------------------------------------------
__device__ __half g_tn[MM*CC];       // LN output  [m][c]
__device__ __half g_q [MM*CC];       // Q [bh][s][d] (pre-scaled)
__device__ __half g_k [MM*CC];       // K [bh][s][d]
__device__ __half g_v [MM*CC];       // V [bh][s][d]
__device__ __half g_ao[MM*CC];       // attn out [m][512]
__device__ __half g_w[4][CC*CC];     // transposed weights [n][k]; 0..2 contiguous = Wqkv[1536][512]

// ---------------------------------------------------------------------------
// helpers
// ---------------------------------------------------------------------------
__device__ __forceinline__ uint32_t s2u(const void* p) {
    uint32_t a;
    asm("{ .reg .u64 t; cvta.to.shared.u64 t, %1; cvt.u32.u64 %0, t; }" : "=r"(a) : "l"(p));
    return a;
}
__device__ __forceinline__ float ex2f(float x) {
    float y; asm("ex2.approx.f32 %0, %1;" : "=f"(y) : "f"(x)); return y;
}
__device__ __forceinline__ uint32_t packh2(float a, float b) {
    __half2 h = __floats2half2_rn(a, b);
    return *(uint32_t*)&h;
}
__device__ __forceinline__ void ldm4(uint32_t r[4], uint32_t addr) {
    asm volatile("ldmatrix.sync.aligned.m8n8.x4.shared.b16 {%0,%1,%2,%3}, [%4];"
        : "=r"(r[0]), "=r"(r[1]), "=r"(r[2]), "=r"(r[3]) : "r"(addr));
}
__device__ __forceinline__ void ldm4t(uint32_t r[4], uint32_t addr) {
    asm volatile("ldmatrix.sync.aligned.m8n8.x4.trans.shared.b16 {%0,%1,%2,%3}, [%4];"
        : "=r"(r[0]), "=r"(r[1]), "=r"(r[2]), "=r"(r[3]) : "r"(addr));
}
__device__ __forceinline__ void mma_f32(float c[4], const uint32_t a[4], const uint32_t b[2]) {
    asm volatile("mma.sync.aligned.m16n8k16.row.col.f32.f16.f16.f32 "
        "{%0,%1,%2,%3}, {%4,%5,%6,%7}, {%8,%9}, {%0,%1,%2,%3};"
        : "+f"(c[0]), "+f"(c[1]), "+f"(c[2]), "+f"(c[3])
        : "r"(a[0]), "r"(a[1]), "r"(a[2]), "r"(a[3]), "r"(b[0]), "r"(b[1]));
}
__device__ __forceinline__ void cpa16(uint32_t s, const void* g) {
    asm volatile("cp.async.cg.shared.global [%0], [%1], 16;" :: "r"(s), "l"(g));
}
#define CP_COMMIT() asm volatile("cp.async.commit_group;" ::: "memory")
template <int N> __device__ __forceinline__ void cpwait() {
    asm volatile("cp.async.wait_group %0;" :: "n"(N) : "memory");
}

// ---------------------------------------------------------------------------
// Fused prep: blocks 0..1023 = weight transpose, 1024..1535 = transpose+LN
// ---------------------------------------------------------------------------
__global__ __launch_bounds__(256) void prep_kernel(
        const float* __restrict__ wq, const float* __restrict__ wk,
        const float* __restrict__ wv, const float* __restrict__ wo,
        const float* __restrict__ x,
        const float* __restrict__ lng, const float* __restrict__ lnb) {
    __shared__ float smem[16*513 + 32];
    const int tid = threadIdx.x;
    const int bid = blockIdx.x;

    if (bid < 1024) {
        float (*t)[33] = (float(*)[33])smem;
        const int z   = bid >> 8;
        const int rem = bid & 255;
        const int k0 = (rem >> 4) * 32, n0 = (rem & 15) * 32;
        const float* src = z==0 ? wq : z==1 ? wk : z==2 ? wv : wo;
        __half* dst = g_w[z];
        const int c = tid & 31, r8 = tid >> 5;
        #pragma unroll
        for (int i = 0; i < 4; i++) {
            int r = r8 + i*8;
            t[r][c] = src[(k0+r)*CC + n0 + c];
        }
        __syncthreads();
        #pragma unroll
        for (int i = 0; i < 4; i++) {
            int r = r8 + i*8;
            dst[(n0+r)*CC + k0 + c] = __float2half(t[c][r]);
        }
    } else {
        float (*tile)[513] = (float(*)[513])smem;
        float* s_mean = smem + 16*513;
        float* s_rstd = s_mean + 16;
        const int id = bid - 1024;
        const int b  = id >> 6;
        const int s0 = (id & 63) * 16;

        const int sI = tid & 15;
        const int cB = tid >> 4;
        for (int c = cB; c < CC; c += 16)
            tile[sI][c] = x[(b*CC + c)*SS + s0 + sI];
        __syncthreads();

        const int w = tid >> 5, lane = tid & 31;
        for (int s = w; s < 16; s += 8) {
            float sum = 0.f, sq = 0.f;
            for (int c = lane; c < CC; c += 32) {
                float v = tile[s][c];
                sum += v; sq += v*v;
            }
            #pragma unroll
            for (int off = 16; off; off >>= 1) {
                sum += __shfl_xor_sync(0xffffffffu, sum, off);
                sq  += __shfl_xor_sync(0xffffffffu, sq,  off);
            }
            if (lane == 0) {
                float mu = sum * (1.f/CC);
                s_mean[s] = mu;
                s_rstd[s] = rsqrtf(sq*(1.f/CC) - mu*mu + 1e-5f);
            }
        }
        __syncthreads();

        for (int i = tid; i < 16*256; i += 256) {
            int s  = i >> 8;
            int c2 = (i & 255) * 2;
            float v0 = (tile[s][c2  ] - s_mean[s]) * s_rstd[s] * lng[c2  ] + lnb[c2  ];
            float v1 = (tile[s][c2+1] - s_mean[s]) * s_rstd[s] * lng[c2+1] + lnb[c2+1];
            *(uint32_t*)&g_tn[((b<<10) + s0 + s)*CC + c2] = packh2(v0, v1);
        }
    }
}

// ---------------------------------------------------------------------------
// fp16 mma.sync GEMM: BM=128 BN=128 BK=64, 128 threads (4 warps, 2M x 2N),
// warp tile 64x64, f32 accum, cp.async 2-stage STATIC smem, one barrier/chunk.
//  MODE 0: A=g_tn, W=Wqkv fused -> Q/K/V [bh][s][d]
//  MODE 1: A=g_ao, W=g_w[3] -> fp32 out + bias + residual(x transposed read)
// ---------------------------------------------------------------------------
template <int MODE>
__global__ __launch_bounds__(128, 2) void mm_kernel(
        const float* __restrict__ bq, const float* __restrict__ bk,
        const float* __restrict__ bv, const float* __restrict__ bo,
        const float* __restrict__ x,  float* __restrict__ dout) {

    __shared__ __half sA[2][128][72];
    __shared__ __half sB[2][128][72];

    const int tid  = threadIdx.x;
    const int lane = tid & 31;
    const int wid  = tid >> 5;
    const int wm   = wid & 1;
    const int wn   = wid >> 1;
    const int m0 = blockIdx.y * 128;
    const int n0 = blockIdx.x * 128;
    const int z  = (MODE == 0) ? (n0 >> 9) : 3;

    const __half* A = (MODE == 0) ? g_tn : g_ao;
    const __half* W = (MODE == 0) ? (g_w[0] + (size_t)n0 * CC)
                                  : (g_w[3] + (size_t)n0 * CC);
    const float* bias = (MODE == 0) ? (z==0 ? bq : z==1 ? bk : bv) : bo;

    float acc[4][8][4];
    #pragma unroll
    for (int i = 0; i < 4; i++)
        #pragma unroll
        for (int j = 0; j < 8; j++)
            #pragma unroll
            for (int q = 0; q < 4; q++) acc[i][j][q] = 0.f;

    auto issue = [&](int st, int k0) {
        #pragma unroll
        for (int i = 0; i < 8; i++) {
            int idx = tid + i*128;
            int row = idx >> 3, seg = idx & 7;
            cpa16(s2u(&sA[st][row][seg*8]), &A[(m0+row)*CC + k0 + seg*8]);
            cpa16(s2u(&sB[st][row][seg*8]), &W[row*CC + k0 + seg*8]);
        }
        CP_COMMIT();
    };

    issue(0, 0);

    for (int kc = 0; kc < 8; kc++) {
        const int st = kc & 1;
        cpwait<0>();
        __syncthreads();
        if (kc < 7) issue(st^1, (kc+1)*64);

        #pragma unroll
        for (int kk = 0; kk < 64; kk += 16) {
            uint32_t af[4][4];
            #pragma unroll
            for (int mt = 0; mt < 4; mt++)
                ldm4(af[mt], s2u(&sA[st][wm*64 + mt*16 + (lane & 15)]
                                        [kk + (lane >> 4)*8]));
            #pragma unroll
            for (int p = 0; p < 4; p++) {
                uint32_t b4[4];
                ldm4(b4, s2u(&sB[st][wn*64 + (p*2 + (lane >> 4))*8 + (lane & 7)]
                                     [kk + ((lane >> 3) & 1)*8]));
                #pragma unroll
                for (int mt = 0; mt < 4; mt++) {
                    mma_f32(acc[mt][2*p  ], af[mt], b4);
                    mma_f32(acc[mt][2*p+1], af[mt], b4+2);
                }
            }
        }
    }

    // epilogue
    #pragma unroll
    for (int mt = 0; mt < 4; mt++) {
        const int r0 = m0 + wm*64 + mt*16 + (lane >> 2);
        const int r1 = r0 + 8;
        const int b0r = r0 >> 10, s0r = r0 & 1023;
        const int b1r = r1 >> 10, s1r = r1 & 1023;
        #pragma unroll
        for (int nt = 0; nt < 8; nt++) {
            const int c  = n0 + wn*64 + nt*8 + (lane & 3)*2;
            const int cz = c & 511;
            float v00 = acc[mt][nt][0] + bias[cz];
            float v01 = acc[mt][nt][1] + bias[cz+1];
            float v10 = acc[mt][nt][2] + bias[cz];
            float v11 = acc[mt][nt][3] + bias[cz+1];

            if (MODE == 0) {
                const int h = cz >> 6, d = c & 63;
                if (z == 0) { v00 *= QSCALE; v01 *= QSCALE; v10 *= QSCALE; v11 *= QSCALE; }
                __half* o = (z == 0) ? g_q : (z == 1) ? g_k : g_v;
                *(uint32_t*)&o[(((b0r*HH + h) << 10) + s0r)*DD + d] = packh2(v00, v01);
                *(uint32_t*)&o[(((b1r*HH + h) << 10) + s1r)*DD + d] = packh2(v10, v11);
            } else {
                float2 o0, o1;
                o0.x = v00 + x[(b0r*CC + c    )*SS + s0r];
                o0.y = v01 + x[(b0r*CC + c + 1)*SS + s0r];
                o1.x = v10 + x[(b1r*CC + c    )*SS + s1r];
                o1.y = v11 + x[(b1r*CC + c + 1)*SS + s1r];
                *(float2*)&dout[r0*CC + c] = o0;
                *(float2*)&dout[r1*CC + c] = o1;
            }
        }
    }
}

// ---------------------------------------------------------------------------
// FA2 attention: fp16 in / f32 accum, 128 threads, 4 warps x 32 q-rows,
// cp.async 2-stage, one barrier per k-tile, 2 CTAs/SM (no reg spills).
// ---------------------------------------------------------------------------
__global__ __launch_bounds__(128, 2) void attn_kernel() {
    __shared__ __half sKV[2][2][64][72];   // [stage][0=K,1=V][s][d]

    const int tid  = threadIdx.x;
    const int lane = tid & 31;
    const int wid  = tid >> 5;
    const int bh   = blockIdx.y;
    const int q0   = blockIdx.x * 128;

    const __half* qg = g_q + (size_t)bh * SS * DD;
    const __half* kg = g_k + (size_t)bh * SS * DD;
    const __half* vg = g_v + (size_t)bh * SS * DD;

    __half (*sQ)[72] = reinterpret_cast<__half(*)[72]>(&sKV[0][0][0][0]);
    #pragma unroll
    for (int i = 0; i < 8; i++) {
        int idx = tid + i*128;
        int row = idx >> 3, seg = idx & 7;
        *(uint4*)&sQ[row][seg*8] = *(const uint4*)&qg[(q0+row)*DD + seg*8];
    }
    __syncthreads();
    uint32_t qf[2][4][4];
    #pragma unroll
    for (int mt = 0; mt < 2; mt++)
        #pragma unroll
        for (int ks = 0; ks < 4; ks++)
            ldm4(qf[mt][ks], s2u(&sQ[wid*32 + mt*16 + (lane & 15)]
                                    [ks*16 + (lane >> 4)*8]));
    __syncthreads();

    float o[2][8][4];
    #pragma unroll
    for (int mt = 0; mt < 2; mt++)
        #pragma unroll
        for (int i = 0; i < 8; i++)
            #pragma unroll
            for (int j = 0; j < 4; j++) o[mt][i][j] = 0.f;
    float lA[2] = {0.f, 0.f}, lB[2] = {0.f, 0.f};

    auto issue = [&](int st, int kt) {
        const int s0 = kt * 64;
        #pragma unroll
        for (int i = 0; i < 4; i++) {
            int idx = tid + i*128;
            int row = idx >> 3, seg = idx & 7;
            cpa16(s2u(&sKV[st][0][row][seg*8]), &kg[(s0+row)*DD + seg*8]);
            cpa16(s2u(&sKV[st][1][row][seg*8]), &vg[(s0+row)*DD + seg*8]);
        }
        CP_COMMIT();
    };

    issue(0, 0);

    for (int kt = 0; kt < 16; kt++) {
        const int st = kt & 1;
        cpwait<0>();
        __syncthreads();
        if (kt < 15) issue(st^1, kt+1);

        #pragma unroll
        for (int j2 = 0; j2 < 4; j2++) {
            float sc[2][2][4];
            #pragma unroll
            for (int mt = 0; mt < 2; mt++)
                #pragma unroll
                for (int n = 0; n < 2; n++)
                    #pragma unroll
                    for (int q = 0; q < 4; q++) sc[mt][n][q] = 0.f;

            #pragma unroll
            for (int ks = 0; ks < 4; ks++) {
                uint32_t b4[4];
                ldm4(b4, s2u(&sKV[st][0][(2*j2 + (lane >> 4))*8 + (lane & 7)]
                                        [ks*16 + ((lane >> 3) & 1)*8]));
                #pragma unroll
                for (int mt = 0; mt < 2; mt++) {
                    mma_f32(sc[mt][0], qf[mt][ks], b4);
                    mma_f32(sc[mt][1], qf[mt][ks], b4+2);
                }
            }

            uint32_t pa[2][4];
            #pragma unroll
            for (int mt = 0; mt < 2; mt++) {
                float e00 = ex2f(sc[mt][0][0]), e01 = ex2f(sc[mt][0][1]);
                float e02 = ex2f(sc[mt][0][2]), e03 = ex2f(sc[mt][0][3]);
                float e10 = ex2f(sc[mt][1][0]), e11 = ex2f(sc[mt][1][1]);
                float e12 = ex2f(sc[mt][1][2]), e13 = ex2f(sc[mt][1][3]);
                lA[mt] += e00 + e01 + e10 + e11;
                lB[mt] += e02 + e03 + e12 + e13;
                pa[mt][0] = packh2(e00, e01);
                pa[mt][1] = packh2(e02, e03);
                pa[mt][2] = packh2(e10, e11);
                pa[mt][3] = packh2(e12, e13);
            }

            #pragma unroll
            for (int p = 0; p < 4; p++) {
                uint32_t v4[4];
                ldm4t(v4, s2u(&sKV[st][1][j2*16 + (lane & 15)]
                                         [(p*2 + (lane >> 4))*8]));
                #pragma unroll
                for (int mt = 0; mt < 2; mt++) {
                    mma_f32(o[mt][2*p  ], pa[mt], v4);
                    mma_f32(o[mt][2*p+1], pa[mt], v4+2);
                }
            }
        }
    }

    const int b = bh >> 3, h = bh & 7;
    #pragma unroll
    for (int mt = 0; mt < 2; mt++) {
        float la = lA[mt], lb = lB[mt];
        la += __shfl_xor_sync(0xffffffffu, la, 1);
        la += __shfl_xor_sync(0xffffffffu, la, 2);
        lb += __shfl_xor_sync(0xffffffffu, lb, 1);
        lb += __shfl_xor_sync(0xffffffffu, lb, 2);
        const float invA = 1.f / la, invB = 1.f / lb;

        const int mA = (b << 10) + q0 + wid*32 + mt*16 + (lane >> 2);
        const int mB = mA + 8;
        #pragma unroll
        for (int nt = 0; nt < 8; nt++) {
            const int d = nt*8 + (lane & 3)*2;
            *(uint32_t*)&g_ao[mA*CC + h*DD + d] =
                packh2(o[mt][nt][0]*invA, o[mt][nt][1]*invA);
            *(uint32_t*)&g_ao[mB*CC + h*DD + d] =
                packh2(o[mt][nt][2]*invB, o[mt][nt][3]*invB);
        }
    }
}

// ---------------------------------------------------------------------------
extern "C" void kernel_launch(void* const* d_in, const int* in_sizes, int n_in,
                              void* d_out, int out_size) {
    const float* x   = (const float*)d_in[0];
    const float* wq  = (const float*)d_in[1];
    const float* bq  = (const float*)d_in[2];
    const float* wk  = (const float*)d_in[3];
    const float* bk  = (const float*)d_in[4];
    const float* wv  = (const float*)d_in[5];
    const float* bv  = (const float*)d_in[6];
    const float* lng = (const float*)d_in[7];
    const float* lnb = (const float*)d_in[8];
    const float* wo  = (const float*)d_in[9];
    const float* bo  = (const float*)d_in[10];
    float* out = (float*)d_out;

    prep_kernel<<<1536, 256>>>(wq, wk, wv, wo, x, lng, lnb);
    mm_kernel<0><<<dim3(12, 64), 128>>>(bq, bk, bv, nullptr, nullptr, nullptr);
    attn_kernel<<<dim3(8, 64), 128>>>();
    mm_kernel<1><<<dim3(4, 64), 128>>>(nullptr, nullptr, nullptr, bo, x, out);
}

// round 16
// speedup vs baseline: 1.0547x; 1.0100x over previous
#include <cuda_runtime.h>
#include <cuda_fp16.h>
#include <math.h>
#include <stdint.h>

#define BB 8
#define CC 512
#define SS 1024
#define HH 8
#define DD 64
#define MM (BB*SS)

#define QSCALE (0.125f * 1.44269504088896340736f)   // 1/(8 ln2) -> softmax via exp2

// ---------------------------------------------------------------------------
// Scratch (device globals) — fp16 storage
// ---------------------------------------------------------------------------
__device__ __half g_tn[MM*CC];       // LN output  [m][c]
__device__ __half g_q [MM*CC];       // Q [bh][s][d] (pre-scaled)
__device__ __half g_k [MM*CC];       // K [bh][s][d]
__device__ __half g_v [MM*CC];       // V [bh][s][d]
__device__ __half g_ao[MM*CC];       // attn out [m][512]
__device__ __half g_w[4][CC*CC];     // transposed weights [n][k]; 0..2 contiguous = Wqkv[1536][512]

// ---------------------------------------------------------------------------
// helpers
// ---------------------------------------------------------------------------
__device__ __forceinline__ uint32_t s2u(const void* p) {
    uint32_t a;
    asm("{ .reg .u64 t; cvta.to.shared.u64 t, %1; cvt.u32.u64 %0, t; }" : "=r"(a) : "l"(p));
    return a;
}
__device__ __forceinline__ uint32_t packh2(float a, float b) {
    __half2 h = __floats2half2_rn(a, b);
    return *(uint32_t*)&h;
}
// pack two f32 -> f16x2 via cvt (lo = a, hi = b)
__device__ __forceinline__ uint32_t cvth2(float a, float b) {
    uint32_t r;
    asm("cvt.rn.f16x2.f32 %0, %1, %2;" : "=r"(r) : "f"(b), "f"(a));
    return r;
}
// packed half2 exp2 — ONE MUFU op for two values
__device__ __forceinline__ uint32_t h2ex2(uint32_t x) {
    uint32_t y;
    asm("ex2.approx.f16x2 %0, %1;" : "=r"(y) : "r"(x));
    return y;
}
__device__ __forceinline__ void ldm4(uint32_t r[4], uint32_t addr) {
    asm volatile("ldmatrix.sync.aligned.m8n8.x4.shared.b16 {%0,%1,%2,%3}, [%4];"
        : "=r"(r[0]), "=r"(r[1]), "=r"(r[2]), "=r"(r[3]) : "r"(addr));
}
__device__ __forceinline__ void ldm4t(uint32_t r[4], uint32_t addr) {
    asm volatile("ldmatrix.sync.aligned.m8n8.x4.trans.shared.b16 {%0,%1,%2,%3}, [%4];"
        : "=r"(r[0]), "=r"(r[1]), "=r"(r[2]), "=r"(r[3]) : "r"(addr));
}
__device__ __forceinline__ void mma_f32(float c[4], const uint32_t a[4], const uint32_t b[2]) {
    asm volatile("mma.sync.aligned.m16n8k16.row.col.f32.f16.f16.f32 "
        "{%0,%1,%2,%3}, {%4,%5,%6,%7}, {%8,%9}, {%0,%1,%2,%3};"
        : "+f"(c[0]), "+f"(c[1]), "+f"(c[2]), "+f"(c[3])
        : "r"(a[0]), "r"(a[1]), "r"(a[2]), "r"(a[3]), "r"(b[0]), "r"(b[1]));
}
__device__ __forceinline__ void cpa16(uint32_t s, const void* g) {
    asm volatile("cp.async.cg.shared.global [%0], [%1], 16;" :: "r"(s), "l"(g));
}
#define CP_COMMIT() asm volatile("cp.async.commit_group;" ::: "memory")
template <int N> __device__ __forceinline__ void cpwait() {
    asm volatile("cp.async.wait_group %0;" :: "n"(N) : "memory");
}

// ---------------------------------------------------------------------------
// Fused prep: blocks 0..1023 = weight transpose, 1024..1535 = transpose+LN
// ---------------------------------------------------------------------------
__global__ __launch_bounds__(256) void prep_kernel(
        const float* __restrict__ wq, const float* __restrict__ wk,
        const float* __restrict__ wv, const float* __restrict__ wo,
        const float* __restrict__ x,
        const float* __restrict__ lng, const float* __restrict__ lnb) {
    __shared__ float smem[16*513 + 32];
    const int tid = threadIdx.x;
    const int bid = blockIdx.x;

    if (bid < 1024) {
        float (*t)[33] = (float(*)[33])smem;
        const int z   = bid >> 8;
        const int rem = bid & 255;
        const int k0 = (rem >> 4) * 32, n0 = (rem & 15) * 32;
        const float* src = z==0 ? wq : z==1 ? wk : z==2 ? wv : wo;
        __half* dst = g_w[z];
        const int c = tid & 31, r8 = tid >> 5;
        #pragma unroll
        for (int i = 0; i < 4; i++) {
            int r = r8 + i*8;
            t[r][c] = src[(k0+r)*CC + n0 + c];
        }
        __syncthreads();
        #pragma unroll
        for (int i = 0; i < 4; i++) {
            int r = r8 + i*8;
            dst[(n0+r)*CC + k0 + c] = __float2half(t[c][r]);
        }
    } else {
        float (*tile)[513] = (float(*)[513])smem;
        float* s_mean = smem + 16*513;
        float* s_rstd = s_mean + 16;
        const int id = bid - 1024;
        const int b  = id >> 6;
        const int s0 = (id & 63) * 16;

        const int sI = tid & 15;
        const int cB = tid >> 4;
        for (int c = cB; c < CC; c += 16)
            tile[sI][c] = x[(b*CC + c)*SS + s0 + sI];
        __syncthreads();

        const int w = tid >> 5, lane = tid & 31;
        for (int s = w; s < 16; s += 8) {
            float sum = 0.f, sq = 0.f;
            for (int c = lane; c < CC; c += 32) {
                float v = tile[s][c];
                sum += v; sq += v*v;
            }
            #pragma unroll
            for (int off = 16; off; off >>= 1) {
                sum += __shfl_xor_sync(0xffffffffu, sum, off);
                sq  += __shfl_xor_sync(0xffffffffu, sq,  off);
            }
            if (lane == 0) {
                float mu = sum * (1.f/CC);
                s_mean[s] = mu;
                s_rstd[s] = rsqrtf(sq*(1.f/CC) - mu*mu + 1e-5f);
            }
        }
        __syncthreads();

        for (int i = tid; i < 16*256; i += 256) {
            int s  = i >> 8;
            int c2 = (i & 255) * 2;
            float v0 = (tile[s][c2  ] - s_mean[s]) * s_rstd[s] * lng[c2  ] + lnb[c2  ];
            float v1 = (tile[s][c2+1] - s_mean[s]) * s_rstd[s] * lng[c2+1] + lnb[c2+1];
            *(uint32_t*)&g_tn[((b<<10) + s0 + s)*CC + c2] = packh2(v0, v1);
        }
    }
}

// ---------------------------------------------------------------------------
// fp16 mma.sync GEMM: BM=128 BN=128 BK=64, 128 threads (4 warps, 2M x 2N),
// warp tile 64x64, f32 accum, cp.async 2-stage STATIC smem, one barrier/chunk.
//  MODE 0: A=g_tn, W=Wqkv fused -> Q/K/V [bh][s][d]
//  MODE 1: A=g_ao, W=g_w[3] -> fp32 out + bias + residual(x transposed read)
// ---------------------------------------------------------------------------
template <int MODE>
__global__ __launch_bounds__(128, 2) void mm_kernel(
        const float* __restrict__ bq, const float* __restrict__ bk,
        const float* __restrict__ bv, const float* __restrict__ bo,
        const float* __restrict__ x,  float* __restrict__ dout) {

    __shared__ __half sA[2][128][72];
    __shared__ __half sB[2][128][72];

    const int tid  = threadIdx.x;
    const int lane = tid & 31;
    const int wid  = tid >> 5;
    const int wm   = wid & 1;
    const int wn   = wid >> 1;
    const int m0 = blockIdx.y * 128;
    const int n0 = blockIdx.x * 128;
    const int z  = (MODE == 0) ? (n0 >> 9) : 3;

    const __half* A = (MODE == 0) ? g_tn : g_ao;
    const __half* W = (MODE == 0) ? (g_w[0] + (size_t)n0 * CC)
                                  : (g_w[3] + (size_t)n0 * CC);
    const float* bias = (MODE == 0) ? (z==0 ? bq : z==1 ? bk : bv) : bo;

    float acc[4][8][4];
    #pragma unroll
    for (int i = 0; i < 4; i++)
        #pragma unroll
        for (int j = 0; j < 8; j++)
            #pragma unroll
            for (int q = 0; q < 4; q++) acc[i][j][q] = 0.f;

    auto issue = [&](int st, int k0) {
        #pragma unroll
        for (int i = 0; i < 8; i++) {
            int idx = tid + i*128;
            int row = idx >> 3, seg = idx & 7;
            cpa16(s2u(&sA[st][row][seg*8]), &A[(m0+row)*CC + k0 + seg*8]);
            cpa16(s2u(&sB[st][row][seg*8]), &W[row*CC + k0 + seg*8]);
        }
        CP_COMMIT();
    };

    issue(0, 0);

    for (int kc = 0; kc < 8; kc++) {
        const int st = kc & 1;
        cpwait<0>();
        __syncthreads();
        if (kc < 7) issue(st^1, (kc+1)*64);

        #pragma unroll
        for (int kk = 0; kk < 64; kk += 16) {
            uint32_t af[4][4];
            #pragma unroll
            for (int mt = 0; mt < 4; mt++)
                ldm4(af[mt], s2u(&sA[st][wm*64 + mt*16 + (lane & 15)]
                                        [kk + (lane >> 4)*8]));
            #pragma unroll
            for (int p = 0; p < 4; p++) {
                uint32_t b4[4];
                ldm4(b4, s2u(&sB[st][wn*64 + (p*2 + (lane >> 4))*8 + (lane & 7)]
                                     [kk + ((lane >> 3) & 1)*8]));
                #pragma unroll
                for (int mt = 0; mt < 4; mt++) {
                    mma_f32(acc[mt][2*p  ], af[mt], b4);
                    mma_f32(acc[mt][2*p+1], af[mt], b4+2);
                }
            }
        }
    }

    // epilogue
    #pragma unroll
    for (int mt = 0; mt < 4; mt++) {
        const int r0 = m0 + wm*64 + mt*16 + (lane >> 2);
        const int r1 = r0 + 8;
        const int b0r = r0 >> 10, s0r = r0 & 1023;
        const int b1r = r1 >> 10, s1r = r1 & 1023;
        #pragma unroll
        for (int nt = 0; nt < 8; nt++) {
            const int c  = n0 + wn*64 + nt*8 + (lane & 3)*2;
            const int cz = c & 511;
            float v00 = acc[mt][nt][0] + bias[cz];
            float v01 = acc[mt][nt][1] + bias[cz+1];
            float v10 = acc[mt][nt][2] + bias[cz];
            float v11 = acc[mt][nt][3] + bias[cz+1];

            if (MODE == 0) {
                const int h = cz >> 6, d = c & 63;
                if (z == 0) { v00 *= QSCALE; v01 *= QSCALE; v10 *= QSCALE; v11 *= QSCALE; }
                __half* o = (z == 0) ? g_q : (z == 1) ? g_k : g_v;
                *(uint32_t*)&o[(((b0r*HH + h) << 10) + s0r)*DD + d] = packh2(v00, v01);
                *(uint32_t*)&o[(((b1r*HH + h) << 10) + s1r)*DD + d] = packh2(v10, v11);
            } else {
                float2 o0, o1;
                o0.x = v00 + x[(b0r*CC + c    )*SS + s0r];
                o0.y = v01 + x[(b0r*CC + c + 1)*SS + s0r];
                o1.x = v10 + x[(b1r*CC + c    )*SS + s1r];
                o1.y = v11 + x[(b1r*CC + c + 1)*SS + s1r];
                *(float2*)&dout[r0*CC + c] = o0;
                *(float2*)&dout[r1*CC + c] = o1;
            }
        }
    }
}

// ---------------------------------------------------------------------------
// FA2 attention: fp16 in / f32 accum, 128 threads, 4 warps x 32 q-rows,
// cp.async 2-stage, one barrier per k-tile, 2 CTAs/SM.
// Softmax via PACKED half2 exp2 (ex2.approx.f16x2) — halves MUFU work.
// ---------------------------------------------------------------------------
__global__ __launch_bounds__(128, 2) void attn_kernel() {
    __shared__ __half sKV[2][2][64][72];   // [stage][0=K,1=V][s][d]

    const int tid  = threadIdx.x;
    const int lane = tid & 31;
    const int wid  = tid >> 5;
    const int bh   = blockIdx.y;
    const int q0   = blockIdx.x * 128;

    const __half* qg = g_q + (size_t)bh * SS * DD;
    const __half* kg = g_k + (size_t)bh * SS * DD;
    const __half* vg = g_v + (size_t)bh * SS * DD;

    __half (*sQ)[72] = reinterpret_cast<__half(*)[72]>(&sKV[0][0][0][0]);
    #pragma unroll
    for (int i = 0; i < 8; i++) {
        int idx = tid + i*128;
        int row = idx >> 3, seg = idx & 7;
        *(uint4*)&sQ[row][seg*8] = *(const uint4*)&qg[(q0+row)*DD + seg*8];
    }
    __syncthreads();
    uint32_t qf[2][4][4];
    #pragma unroll
    for (int mt = 0; mt < 2; mt++)
        #pragma unroll
        for (int ks = 0; ks < 4; ks++)
            ldm4(qf[mt][ks], s2u(&sQ[wid*32 + mt*16 + (lane & 15)]
                                    [ks*16 + (lane >> 4)*8]));
    __syncthreads();

    float o[2][8][4];
    #pragma unroll
    for (int mt = 0; mt < 2; mt++)
        #pragma unroll
        for (int i = 0; i < 8; i++)
            #pragma unroll
            for (int j = 0; j < 4; j++) o[mt][i][j] = 0.f;
    float lA[2] = {0.f, 0.f}, lB[2] = {0.f, 0.f};

    auto issue = [&](int st, int kt) {
        const int s0 = kt * 64;
        #pragma unroll
        for (int i = 0; i < 4; i++) {
            int idx = tid + i*128;
            int row = idx >> 3, seg = idx & 7;
            cpa16(s2u(&sKV[st][0][row][seg*8]), &kg[(s0+row)*DD + seg*8]);
            cpa16(s2u(&sKV[st][1][row][seg*8]), &vg[(s0+row)*DD + seg*8]);
        }
        CP_COMMIT();
    };

    issue(0, 0);

    for (int kt = 0; kt < 16; kt++) {
        const int st = kt & 1;
        cpwait<0>();
        __syncthreads();
        if (kt < 15) issue(st^1, kt+1);

        #pragma unroll
        for (int j2 = 0; j2 < 4; j2++) {
            float sc[2][2][4];
            #pragma unroll
            for (int mt = 0; mt < 2; mt++)
                #pragma unroll
                for (int n = 0; n < 2; n++)
                    #pragma unroll
                    for (int q = 0; q < 4; q++) sc[mt][n][q] = 0.f;

            #pragma unroll
            for (int ks = 0; ks < 4; ks++) {
                uint32_t b4[4];
                ldm4(b4, s2u(&sKV[st][0][(2*j2 + (lane >> 4))*8 + (lane & 7)]
                                        [ks*16 + ((lane >> 3) & 1)*8]));
                #pragma unroll
                for (int mt = 0; mt < 2; mt++) {
                    mma_f32(sc[mt][0], qf[mt][ks], b4);
                    mma_f32(sc[mt][1], qf[mt][ks], b4+2);
                }
            }

            // P = exp2(S) via packed half2 MUFU; l sums via hadd2 + f32
            uint32_t pa[2][4];
            #pragma unroll
            for (int mt = 0; mt < 2; mt++) {
                pa[mt][0] = h2ex2(cvth2(sc[mt][0][0], sc[mt][0][1]));  // rowA nt0
                pa[mt][1] = h2ex2(cvth2(sc[mt][0][2], sc[mt][0][3]));  // rowB nt0
                pa[mt][2] = h2ex2(cvth2(sc[mt][1][0], sc[mt][1][1]));  // rowA nt1
                pa[mt][3] = h2ex2(cvth2(sc[mt][1][2], sc[mt][1][3]));  // rowB nt1
                __half2 sa = __hadd2(*(__half2*)&pa[mt][0], *(__half2*)&pa[mt][2]);
                __half2 sb = __hadd2(*(__half2*)&pa[mt][1], *(__half2*)&pa[mt][3]);
                float2 fa = __half22float2(sa);
                float2 fb = __half22float2(sb);
                lA[mt] += fa.x + fa.y;
                lB[mt] += fb.x + fb.y;
            }

            #pragma unroll
            for (int p = 0; p < 4; p++) {
                uint32_t v4[4];
                ldm4t(v4, s2u(&sKV[st][1][j2*16 + (lane & 15)]
                                         [(p*2 + (lane >> 4))*8]));
                #pragma unroll
                for (int mt = 0; mt < 2; mt++) {
                    mma_f32(o[mt][2*p  ], pa[mt], v4);
                    mma_f32(o[mt][2*p+1], pa[mt], v4+2);
                }
            }
        }
    }

    const int b = bh >> 3, h = bh & 7;
    #pragma unroll
    for (int mt = 0; mt < 2; mt++) {
        float la = lA[mt], lb = lB[mt];
        la += __shfl_xor_sync(0xffffffffu, la, 1);
        la += __shfl_xor_sync(0xffffffffu, la, 2);
        lb += __shfl_xor_sync(0xffffffffu, lb, 1);
        lb += __shfl_xor_sync(0xffffffffu, lb, 2);
        const float invA = 1.f / la, invB = 1.f / lb;

        const int mA = (b << 10) + q0 + wid*32 + mt*16 + (lane >> 2);
        const int mB = mA + 8;
        #pragma unroll
        for (int nt = 0; nt < 8; nt++) {
            const int d = nt*8 + (lane & 3)*2;
            *(uint32_t*)&g_ao[mA*CC + h*DD + d] =
                packh2(o[mt][nt][0]*invA, o[mt][nt][1]*invA);
            *(uint32_t*)&g_ao[mB*CC + h*DD + d] =
                packh2(o[mt][nt][2]*invB, o[mt][nt][3]*invB);
        }
    }
}

// ---------------------------------------------------------------------------
extern "C" void kernel_launch(void* const* d_in, const int* in_sizes, int n_in,
                              void* d_out, int out_size) {
    const float* x   = (const float*)d_in[0];
    const float* wq  = (const float*)d_in[1];
    const float* bq  = (const float*)d_in[2];
    const float* wk  = (const float*)d_in[3];
    const float* bk  = (const float*)d_in[4];
    const float* wv  = (const float*)d_in[5];
    const float* bv  = (const float*)d_in[6];
    const float* lng = (const float*)d_in[7];
    const float* lnb = (const float*)d_in[8];
    const float* wo  = (const float*)d_in[9];
    const float* bo  = (const float*)d_in[10];
    float* out = (float*)d_out;

    prep_kernel<<<1536, 256>>>(wq, wk, wv, wo, x, lng, lnb);
    mm_kernel<0><<<dim3(12, 64), 128>>>(bq, bk, bv, nullptr, nullptr, nullptr);
    attn_kernel<<<dim3(8, 64), 128>>>();
    mm_kernel<1><<<dim3(4, 64), 128>>>(nullptr, nullptr, nullptr, bo, x, out);
}

// round 17
// speedup vs baseline: 1.0577x; 1.0028x over previous
#include <cuda_runtime.h>
#include <cuda_fp16.h>
#include <math.h>
#include <stdint.h>

#define BB 8
#define CC 512
#define SS 1024
#define HH 8
#define DD 64
#define MM (BB*SS)

#define QSCALE (0.125f * 1.44269504088896340736f)   // 1/(8 ln2) -> softmax via exp2

// ---------------------------------------------------------------------------
// Scratch (device globals) — fp16 storage
// ---------------------------------------------------------------------------
__device__ __half g_tn[MM*CC];       // LN output  [m][c]
__device__ __half g_q [MM*CC];       // Q [bh][s][d] (pre-scaled)
__device__ __half g_k [MM*CC];       // K [bh][s][d]
__device__ __half g_v [MM*CC];       // V [bh][s][d]
__device__ __half g_ao[MM*CC];       // attn out [m][512]
__device__ __half g_w[4][CC*CC];     // transposed weights [n][k]; 0..2 contiguous = Wqkv[1536][512]

// ---------------------------------------------------------------------------
// helpers
// ---------------------------------------------------------------------------
__device__ __forceinline__ uint32_t s2u(const void* p) {
    uint32_t a;
    asm("{ .reg .u64 t; cvta.to.shared.u64 t, %1; cvt.u32.u64 %0, t; }" : "=r"(a) : "l"(p));
    return a;
}
__device__ __forceinline__ uint32_t packh2(float a, float b) {
    __half2 h = __floats2half2_rn(a, b);
    return *(uint32_t*)&h;
}
__device__ __forceinline__ uint32_t cvth2(float a, float b) {
    uint32_t r;
    asm("cvt.rn.f16x2.f32 %0, %1, %2;" : "=r"(r) : "f"(b), "f"(a));
    return r;
}
__device__ __forceinline__ uint32_t h2ex2(uint32_t x) {
    uint32_t y;
    asm("ex2.approx.f16x2 %0, %1;" : "=r"(y) : "r"(x));
    return y;
}
__device__ __forceinline__ void ldm4(uint32_t r[4], uint32_t addr) {
    asm volatile("ldmatrix.sync.aligned.m8n8.x4.shared.b16 {%0,%1,%2,%3}, [%4];"
        : "=r"(r[0]), "=r"(r[1]), "=r"(r[2]), "=r"(r[3]) : "r"(addr));
}
__device__ __forceinline__ void ldm4t(uint32_t r[4], uint32_t addr) {
    asm volatile("ldmatrix.sync.aligned.m8n8.x4.trans.shared.b16 {%0,%1,%2,%3}, [%4];"
        : "=r"(r[0]), "=r"(r[1]), "=r"(r[2]), "=r"(r[3]) : "r"(addr));
}
__device__ __forceinline__ void mma_f32(float c[4], const uint32_t a[4], const uint32_t b[2]) {
    asm volatile("mma.sync.aligned.m16n8k16.row.col.f32.f16.f16.f32 "
        "{%0,%1,%2,%3}, {%4,%5,%6,%7}, {%8,%9}, {%0,%1,%2,%3};"
        : "+f"(c[0]), "+f"(c[1]), "+f"(c[2]), "+f"(c[3])
        : "r"(a[0]), "r"(a[1]), "r"(a[2]), "r"(a[3]), "r"(b[0]), "r"(b[1]));
}
__device__ __forceinline__ void cpa16(uint32_t s, const void* g) {
    asm volatile("cp.async.cg.shared.global [%0], [%1], 16;" :: "r"(s), "l"(g));
}
#define CP_COMMIT() asm volatile("cp.async.commit_group;" ::: "memory")
template <int N> __device__ __forceinline__ void cpwait() {
    asm volatile("cp.async.wait_group %0;" :: "n"(N) : "memory");
}

// ---------------------------------------------------------------------------
// Fused prep: blocks 0..1023 = weight transpose, 1024..1535 = transpose+LN
// ---------------------------------------------------------------------------
__global__ __launch_bounds__(256) void prep_kernel(
        const float* __restrict__ wq, const float* __restrict__ wk,
        const float* __restrict__ wv, const float* __restrict__ wo,
        const float* __restrict__ x,
        const float* __restrict__ lng, const float* __restrict__ lnb) {
    __shared__ float smem[16*513 + 32];
    const int tid = threadIdx.x;
    const int bid = blockIdx.x;

    if (bid < 1024) {
        float (*t)[33] = (float(*)[33])smem;
        const int z   = bid >> 8;
        const int rem = bid & 255;
        const int k0 = (rem >> 4) * 32, n0 = (rem & 15) * 32;
        const float* src = z==0 ? wq : z==1 ? wk : z==2 ? wv : wo;
        __half* dst = g_w[z];
        const int c = tid & 31, r8 = tid >> 5;
        #pragma unroll
        for (int i = 0; i < 4; i++) {
            int r = r8 + i*8;
            t[r][c] = src[(k0+r)*CC + n0 + c];
        }
        __syncthreads();
        #pragma unroll
        for (int i = 0; i < 4; i++) {
            int r = r8 + i*8;
            dst[(n0+r)*CC + k0 + c] = __float2half(t[c][r]);
        }
    } else {
        float (*tile)[513] = (float(*)[513])smem;
        float* s_mean = smem + 16*513;
        float* s_rstd = s_mean + 16;
        const int id = bid - 1024;
        const int b  = id >> 6;
        const int s0 = (id & 63) * 16;

        const int sI = tid & 15;
        const int cB = tid >> 4;
        for (int c = cB; c < CC; c += 16)
            tile[sI][c] = x[(b*CC + c)*SS + s0 + sI];
        __syncthreads();

        const int w = tid >> 5, lane = tid & 31;
        for (int s = w; s < 16; s += 8) {
            float sum = 0.f, sq = 0.f;
            for (int c = lane; c < CC; c += 32) {
                float v = tile[s][c];
                sum += v; sq += v*v;
            }
            #pragma unroll
            for (int off = 16; off; off >>= 1) {
                sum += __shfl_xor_sync(0xffffffffu, sum, off);
                sq  += __shfl_xor_sync(0xffffffffu, sq,  off);
            }
            if (lane == 0) {
                float mu = sum * (1.f/CC);
                s_mean[s] = mu;
                s_rstd[s] = rsqrtf(sq*(1.f/CC) - mu*mu + 1e-5f);
            }
        }
        __syncthreads();

        for (int i = tid; i < 16*256; i += 256) {
            int s  = i >> 8;
            int c2 = (i & 255) * 2;
            float v0 = (tile[s][c2  ] - s_mean[s]) * s_rstd[s] * lng[c2  ] + lnb[c2  ];
            float v1 = (tile[s][c2+1] - s_mean[s]) * s_rstd[s] * lng[c2+1] + lnb[c2+1];
            *(uint32_t*)&g_tn[((b<<10) + s0 + s)*CC + c2] = packh2(v0, v1);
        }
    }
}

// ---------------------------------------------------------------------------
// fp16 mma.sync GEMM: BM=128 BN=64 BK=64, 128 threads (4 warps, 2M x 2N),
// warp tile 64x32 (acc=64 regs), f32 accum, cp.async 2-stage static smem,
// one barrier/chunk, 3 CTAs/SM (12 warps + register slack).
//  MODE 0: A=g_tn, W=Wqkv fused -> Q/K/V [bh][s][d]
//  MODE 1: A=g_ao, W=g_w[3] -> fp32 out + bias + residual(x transposed read)
// ---------------------------------------------------------------------------
template <int MODE>
__global__ __launch_bounds__(128, 3) void mm_kernel(
        const float* __restrict__ bq, const float* __restrict__ bk,
        const float* __restrict__ bv, const float* __restrict__ bo,
        const float* __restrict__ x,  float* __restrict__ dout) {

    __shared__ __half sA[2][128][72];
    __shared__ __half sB[2][64][72];

    const int tid  = threadIdx.x;
    const int lane = tid & 31;
    const int wid  = tid >> 5;
    const int wm   = wid & 1;     // 2 warps along M, 64 rows each
    const int wn   = wid >> 1;    // 2 warps along N, 32 cols each
    const int m0 = blockIdx.y * 128;
    const int n0 = blockIdx.x * 64;
    const int z  = (MODE == 0) ? (n0 >> 9) : 3;

    const __half* A = (MODE == 0) ? g_tn : g_ao;
    const __half* W = (MODE == 0) ? (g_w[0] + (size_t)n0 * CC)
                                  : (g_w[3] + (size_t)n0 * CC);
    const float* bias = (MODE == 0) ? (z==0 ? bq : z==1 ? bk : bv) : bo;

    float acc[4][4][4];
    #pragma unroll
    for (int i = 0; i < 4; i++)
        #pragma unroll
        for (int j = 0; j < 4; j++)
            #pragma unroll
            for (int q = 0; q < 4; q++) acc[i][j][q] = 0.f;

    auto issue = [&](int st, int k0) {
        #pragma unroll
        for (int i = 0; i < 8; i++) {
            int idx = tid + i*128;
            int row = idx >> 3, seg = idx & 7;
            cpa16(s2u(&sA[st][row][seg*8]), &A[(m0+row)*CC + k0 + seg*8]);
        }
        #pragma unroll
        for (int i = 0; i < 4; i++) {
            int idx = tid + i*128;
            int row = idx >> 3, seg = idx & 7;
            cpa16(s2u(&sB[st][row][seg*8]), &W[row*CC + k0 + seg*8]);
        }
        CP_COMMIT();
    };

    issue(0, 0);

    for (int kc = 0; kc < 8; kc++) {
        const int st = kc & 1;
        cpwait<0>();
        __syncthreads();
        if (kc < 7) issue(st^1, (kc+1)*64);

        #pragma unroll
        for (int kk = 0; kk < 64; kk += 16) {
            uint32_t af[4][4];
            #pragma unroll
            for (int mt = 0; mt < 4; mt++)
                ldm4(af[mt], s2u(&sA[st][wm*64 + mt*16 + (lane & 15)]
                                        [kk + (lane >> 4)*8]));
            #pragma unroll
            for (int p = 0; p < 2; p++) {
                uint32_t b4[4];
                ldm4(b4, s2u(&sB[st][wn*32 + (p*2 + (lane >> 4))*8 + (lane & 7)]
                                     [kk + ((lane >> 3) & 1)*8]));
                #pragma unroll
                for (int mt = 0; mt < 4; mt++) {
                    mma_f32(acc[mt][2*p  ], af[mt], b4);
                    mma_f32(acc[mt][2*p+1], af[mt], b4+2);
                }
            }
        }
    }

    // epilogue
    #pragma unroll
    for (int mt = 0; mt < 4; mt++) {
        const int r0 = m0 + wm*64 + mt*16 + (lane >> 2);
        const int r1 = r0 + 8;
        const int b0r = r0 >> 10, s0r = r0 & 1023;
        const int b1r = r1 >> 10, s1r = r1 & 1023;
        #pragma unroll
        for (int nt = 0; nt < 4; nt++) {
            const int c  = n0 + wn*32 + nt*8 + (lane & 3)*2;
            const int cz = c & 511;
            float v00 = acc[mt][nt][0] + bias[cz];
            float v01 = acc[mt][nt][1] + bias[cz+1];
            float v10 = acc[mt][nt][2] + bias[cz];
            float v11 = acc[mt][nt][3] + bias[cz+1];

            if (MODE == 0) {
                const int h = cz >> 6, d = c & 63;
                if (z == 0) { v00 *= QSCALE; v01 *= QSCALE; v10 *= QSCALE; v11 *= QSCALE; }
                __half* o = (z == 0) ? g_q : (z == 1) ? g_k : g_v;
                *(uint32_t*)&o[(((b0r*HH + h) << 10) + s0r)*DD + d] = packh2(v00, v01);
                *(uint32_t*)&o[(((b1r*HH + h) << 10) + s1r)*DD + d] = packh2(v10, v11);
            } else {
                float2 o0, o1;
                o0.x = v00 + x[(b0r*CC + c    )*SS + s0r];
                o0.y = v01 + x[(b0r*CC + c + 1)*SS + s0r];
                o1.x = v10 + x[(b1r*CC + c    )*SS + s1r];
                o1.y = v11 + x[(b1r*CC + c + 1)*SS + s1r];
                *(float2*)&dout[r0*CC + c] = o0;
                *(float2*)&dout[r1*CC + c] = o1;
            }
        }
    }
}

// ---------------------------------------------------------------------------
// FA2 attention: fp16 in / f32 accum, 128 threads, 4 warps x 32 q-rows,
// cp.async 2-stage, one barrier per k-tile, 2 CTAs/SM. f16x2 packed exp2.
// (R16 structure, unchanged)
// ---------------------------------------------------------------------------
__global__ __launch_bounds__(128, 2) void attn_kernel() {
    __shared__ __half sKV[2][2][64][72];   // [stage][0=K,1=V][s][d]

    const int tid  = threadIdx.x;
    const int lane = tid & 31;
    const int wid  = tid >> 5;
    const int bh   = blockIdx.y;
    const int q0   = blockIdx.x * 128;

    const __half* qg = g_q + (size_t)bh * SS * DD;
    const __half* kg = g_k + (size_t)bh * SS * DD;
    const __half* vg = g_v + (size_t)bh * SS * DD;

    __half (*sQ)[72] = reinterpret_cast<__half(*)[72]>(&sKV[0][0][0][0]);
    #pragma unroll
    for (int i = 0; i < 8; i++) {
        int idx = tid + i*128;
        int row = idx >> 3, seg = idx & 7;
        *(uint4*)&sQ[row][seg*8] = *(const uint4*)&qg[(q0+row)*DD + seg*8];
    }
    __syncthreads();
    uint32_t qf[2][4][4];
    #pragma unroll
    for (int mt = 0; mt < 2; mt++)
        #pragma unroll
        for (int ks = 0; ks < 4; ks++)
            ldm4(qf[mt][ks], s2u(&sQ[wid*32 + mt*16 + (lane & 15)]
                                    [ks*16 + (lane >> 4)*8]));
    __syncthreads();

    float o[2][8][4];
    #pragma unroll
    for (int mt = 0; mt < 2; mt++)
        #pragma unroll
        for (int i = 0; i < 8; i++)
            #pragma unroll
            for (int j = 0; j < 4; j++) o[mt][i][j] = 0.f;
    float lA[2] = {0.f, 0.f}, lB[2] = {0.f, 0.f};

    auto issue = [&](int st, int kt) {
        const int s0 = kt * 64;
        #pragma unroll
        for (int i = 0; i < 4; i++) {
            int idx = tid + i*128;
            int row = idx >> 3, seg = idx & 7;
            cpa16(s2u(&sKV[st][0][row][seg*8]), &kg[(s0+row)*DD + seg*8]);
            cpa16(s2u(&sKV[st][1][row][seg*8]), &vg[(s0+row)*DD + seg*8]);
        }
        CP_COMMIT();
    };

    issue(0, 0);

    for (int kt = 0; kt < 16; kt++) {
        const int st = kt & 1;
        cpwait<0>();
        __syncthreads();
        if (kt < 15) issue(st^1, kt+1);

        #pragma unroll
        for (int j2 = 0; j2 < 4; j2++) {
            float sc[2][2][4];
            #pragma unroll
            for (int mt = 0; mt < 2; mt++)
                #pragma unroll
                for (int n = 0; n < 2; n++)
                    #pragma unroll
                    for (int q = 0; q < 4; q++) sc[mt][n][q] = 0.f;

            #pragma unroll
            for (int ks = 0; ks < 4; ks++) {
                uint32_t b4[4];
                ldm4(b4, s2u(&sKV[st][0][(2*j2 + (lane >> 4))*8 + (lane & 7)]
                                        [ks*16 + ((lane >> 3) & 1)*8]));
                #pragma unroll
                for (int mt = 0; mt < 2; mt++) {
                    mma_f32(sc[mt][0], qf[mt][ks], b4);
                    mma_f32(sc[mt][1], qf[mt][ks], b4+2);
                }
            }

            uint32_t pa[2][4];
            #pragma unroll
            for (int mt = 0; mt < 2; mt++) {
                pa[mt][0] = h2ex2(cvth2(sc[mt][0][0], sc[mt][0][1]));
                pa[mt][1] = h2ex2(cvth2(sc[mt][0][2], sc[mt][0][3]));
                pa[mt][2] = h2ex2(cvth2(sc[mt][1][0], sc[mt][1][1]));
                pa[mt][3] = h2ex2(cvth2(sc[mt][1][2], sc[mt][1][3]));
                __half2 sa = __hadd2(*(__half2*)&pa[mt][0], *(__half2*)&pa[mt][2]);
                __half2 sb = __hadd2(*(__half2*)&pa[mt][1], *(__half2*)&pa[mt][3]);
                float2 fa = __half22float2(sa);
                float2 fb = __half22float2(sb);
                lA[mt] += fa.x + fa.y;
                lB[mt] += fb.x + fb.y;
            }

            #pragma unroll
            for (int p = 0; p < 4; p++) {
                uint32_t v4[4];
                ldm4t(v4, s2u(&sKV[st][1][j2*16 + (lane & 15)]
                                         [(p*2 + (lane >> 4))*8]));
                #pragma unroll
                for (int mt = 0; mt < 2; mt++) {
                    mma_f32(o[mt][2*p  ], pa[mt], v4);
                    mma_f32(o[mt][2*p+1], pa[mt], v4+2);
                }
            }
        }
    }

    const int b = bh >> 3, h = bh & 7;
    #pragma unroll
    for (int mt = 0; mt < 2; mt++) {
        float la = lA[mt], lb = lB[mt];
        la += __shfl_xor_sync(0xffffffffu, la, 1);
        la += __shfl_xor_sync(0xffffffffu, la, 2);
        lb += __shfl_xor_sync(0xffffffffu, lb, 1);
        lb += __shfl_xor_sync(0xffffffffu, lb, 2);
        const float invA = 1.f / la, invB = 1.f / lb;

        const int mA = (b << 10) + q0 + wid*32 + mt*16 + (lane >> 2);
        const int mB = mA + 8;
        #pragma unroll
        for (int nt = 0; nt < 8; nt++) {
            const int d = nt*8 + (lane & 3)*2;
            *(uint32_t*)&g_ao[mA*CC + h*DD + d] =
                packh2(o[mt][nt][0]*invA, o[mt][nt][1]*invA);
            *(uint32_t*)&g_ao[mB*CC + h*DD + d] =
                packh2(o[mt][nt][2]*invB, o[mt][nt][3]*invB);
        }
    }
}

// ---------------------------------------------------------------------------
extern "C" void kernel_launch(void* const* d_in, const int* in_sizes, int n_in,
                              void* d_out, int out_size) {
    const float* x   = (const float*)d_in[0];
    const float* wq  = (const float*)d_in[1];
    const float* bq  = (const float*)d_in[2];
    const float* wk  = (const float*)d_in[3];
    const float* bk  = (const float*)d_in[4];
    const float* wv  = (const float*)d_in[5];
    const float* bv  = (const float*)d_in[6];
    const float* lng = (const float*)d_in[7];
    const float* lnb = (const float*)d_in[8];
    const float* wo  = (const float*)d_in[9];
    const float* bo  = (const float*)d_in[10];
    float* out = (float*)d_out;

    prep_kernel<<<1536, 256>>>(wq, wk, wv, wo, x, lng, lnb);
    mm_kernel<0><<<dim3(24, 64), 128>>>(bq, bk, bv, nullptr, nullptr, nullptr);
    attn_kernel<<<dim3(8, 64), 128>>>();
    mm_kernel<1><<<dim3(8, 64), 128>>>(nullptr, nullptr, nullptr, bo, x, out);
}